// round 10
// baseline (speedup 1.0000x reference)
#include <cuda_runtime.h>
#include <cuda_bf16.h>

// roi_feature: dual bilinear grid_sample with a shared 16x16 grid per batch.
// inputs: [0] original_features f32 (32,256,64,64)
//         [1] lab f32 (32,1,5)
//         [2] attack_features f32 (32,256,64,64)
// output: concat(out1, out2), each (32,256,16,16) f32.
//
// R7 strategy: cut L1tex wavefronts. The x0/x1 corner pair lies in the
// aligned float4 window [a..a+3], a = xc0 & ~3, except when d1==4 (25%),
// handled by a predicated scalar load. One LDG.128 + rare LDG.32 per row
// replaces two scattered LDG.32s -> ~35% fewer L1tex wavefronts, which is
// the binding resource (timed loop runs L2-warm; wf count ~= observed dur).

#define B_   32
#define C_   256
#define H_   64
#define W_   64
#define BIN_ 16
#define CH_PER_BLK 4

// select element d (0..4) from {v.x,v.y,v.z,v.w,e}
__device__ __forceinline__ float pick5(float4 v, float e, int d)
{
    float f = v.x;
    f = (d == 1) ? v.y : f;
    f = (d == 2) ? v.z : f;
    f = (d == 3) ? v.w : f;
    f = (d == 4) ? e   : f;
    return f;
}

__global__ __launch_bounds__(256, 2)
void roi_feature_kernel(const float* __restrict__ orig,
                        const float* __restrict__ lab,
                        const float* __restrict__ att,
                        float* __restrict__ out)
{
    const int b      = blockIdx.x;           // 0..31
    const int cchunk = blockIdx.y;           // 0..63, 4 channels each
    const int t      = threadIdx.x;          // 0..255
    const int i      = t >> 4;               // bin row  (drives y)
    const int j      = t & 15;               // bin col  (drives x)

    const float* L = lab + b * 5;
    const float l1 = __ldg(L + 1);
    const float l2 = __ldg(L + 2);
    const float l3 = __ldg(L + 3);
    const float l4 = __ldg(L + 4);

    // grid[...,0] -> x pixel (from j); grid[...,1] -> y pixel (from i)
    const float gx = 2.0f * (float)(j - BIN_ / 2) * l3 / (float)BIN_ + (l1 * 2.0f - 1.0f);
    const float gy = 2.0f * (float)(i - BIN_ / 2) * l4 / (float)BIN_ + (l2 * 2.0f - 1.0f);

    const float x = ((gx + 1.0f) * (float)W_ - 1.0f) * 0.5f;
    const float y = ((gy + 1.0f) * (float)H_ - 1.0f) * 0.5f;

    const float x0f = floorf(x);
    const float y0f = floorf(y);
    const int x0 = (int)x0f;
    const int y0 = (int)y0f;
    const int x1 = x0 + 1;
    const int y1 = y0 + 1;

    const float wx1 = x - x0f, wx0 = 1.0f - wx1;
    const float wy1 = y - y0f, wy0 = 1.0f - wy1;

    const float vx0 = (x0 >= 0 && x0 < W_) ? 1.0f : 0.0f;
    const float vx1 = (x1 >= 0 && x1 < W_) ? 1.0f : 0.0f;
    const float vy0 = (y0 >= 0 && y0 < H_) ? 1.0f : 0.0f;
    const float vy1 = (y1 >= 0 && y1 < H_) ? 1.0f : 0.0f;

    const float w00 = wx0 * wy0 * vx0 * vy0;
    const float w01 = wx1 * wy0 * vx1 * vy0;
    const float w10 = wx0 * wy1 * vx0 * vy1;
    const float w11 = wx1 * wy1 * vx1 * vy1;

    const int xc0 = min(max(x0, 0), W_ - 1);
    const int xc1 = min(max(x1, 0), W_ - 1);
    const int yc0 = min(max(y0, 0), H_ - 1);
    const int yc1 = min(max(y1, 0), H_ - 1);

    // aligned float4 window covering xc0 (and xc1 unless d1 == 4)
    const int a  = xc0 & ~3;
    const int d0 = xc0 - a;       // 0..3
    const int d1 = xc1 - a;       // 0..4
    const bool needE = (d1 == 4); // then xc1 = a+4 <= 63, in-bounds

    const int r0 = yc0 * W_ + a;
    const int r1 = yc1 * W_ + a;

    const size_t plane   = (size_t)H_ * W_;                     // 4096
    const size_t base    = ((size_t)b * C_ + (size_t)cchunk * CH_PER_BLK) * plane;
    const size_t outbase = ((size_t)b * C_ + (size_t)cchunk * CH_PER_BLK) * (BIN_ * BIN_) + t;
    const size_t out2off = (size_t)B_ * C_ * BIN_ * BIN_;       // 2,097,152

    // ---------------- orig tensor ----------------
    {
        float4 V0[CH_PER_BLK], V1[CH_PER_BLK];
        float  E0[CH_PER_BLK], E1[CH_PER_BLK];
        #pragma unroll
        for (int cc = 0; cc < CH_PER_BLK; ++cc) {
            const float* pp = orig + base + (size_t)cc * plane;
            V0[cc] = __ldg((const float4*)(pp + r0));
            V1[cc] = __ldg((const float4*)(pp + r1));
        }
        #pragma unroll
        for (int cc = 0; cc < CH_PER_BLK; ++cc) {
            const float* pp = orig + base + (size_t)cc * plane;
            E0[cc] = needE ? __ldg(pp + r0 + 4) : 0.0f;
            E1[cc] = needE ? __ldg(pp + r1 + 4) : 0.0f;
        }
        #pragma unroll
        for (int cc = 0; cc < CH_PER_BLK; ++cc) {
            const float f00 = pick5(V0[cc], E0[cc], d0);
            const float f01 = pick5(V0[cc], E0[cc], d1);
            const float f10 = pick5(V1[cc], E1[cc], d0);
            const float f11 = pick5(V1[cc], E1[cc], d1);
            const float r = f00 * w00 + f01 * w01 + f10 * w10 + f11 * w11;
            out[outbase + (size_t)cc * (BIN_ * BIN_)] = r;
        }
    }

    // ---------------- attack tensor ----------------
    {
        float4 V0[CH_PER_BLK], V1[CH_PER_BLK];
        float  E0[CH_PER_BLK], E1[CH_PER_BLK];
        #pragma unroll
        for (int cc = 0; cc < CH_PER_BLK; ++cc) {
            const float* qq = att + base + (size_t)cc * plane;
            V0[cc] = __ldg((const float4*)(qq + r0));
            V1[cc] = __ldg((const float4*)(qq + r1));
        }
        #pragma unroll
        for (int cc = 0; cc < CH_PER_BLK; ++cc) {
            const float* qq = att + base + (size_t)cc * plane;
            E0[cc] = needE ? __ldg(qq + r0 + 4) : 0.0f;
            E1[cc] = needE ? __ldg(qq + r1 + 4) : 0.0f;
        }
        #pragma unroll
        for (int cc = 0; cc < CH_PER_BLK; ++cc) {
            const float f00 = pick5(V0[cc], E0[cc], d0);
            const float f01 = pick5(V0[cc], E0[cc], d1);
            const float f10 = pick5(V1[cc], E1[cc], d0);
            const float f11 = pick5(V1[cc], E1[cc], d1);
            const float r = f00 * w00 + f01 * w01 + f10 * w10 + f11 * w11;
            out[out2off + outbase + (size_t)cc * (BIN_ * BIN_)] = r;
        }
    }
}

extern "C" void kernel_launch(void* const* d_in, const int* in_sizes, int n_in,
                              void* d_out, int out_size)
{
    const float* orig = (const float*)d_in[0];
    const float* lab  = (const float*)d_in[1];
    const float* att  = (const float*)d_in[2];
    float* out        = (float*)d_out;

    dim3 grid(B_, C_ / CH_PER_BLK);   // (32, 64)
    roi_feature_kernel<<<grid, 256>>>(orig, lab, att, out);
}

// round 11
// speedup vs baseline: 1.3113x; 1.3113x over previous
#include <cuda_runtime.h>
#include <cuda_bf16.h>

// roi_feature: dual bilinear grid_sample with a shared 16x16 grid per batch.
// inputs: [0] original_features f32 (32,256,64,64)
//         [1] lab f32 (32,1,5)
//         [2] attack_features f32 (32,256,64,64)
// output: concat(out1, out2), each (32,256,16,16) f32.
//
// R11 strategy: exact R2 structure (best known: 12.77us; front-batched 32
// gather loads, CH_PER_BLK=4, launch_bounds(256,4)) with ONE change:
// output stores use __stcs (evict-first streaming). The timed loop runs
// L2-warm across graph replays; the 16MB/replay output stream was evicting
// the 72MB input footprint from L2 (88MB vs 126MB capacity). Streaming
// stores protect the warm input lines -> fewer DRAM refills per replay.

#define B_   32
#define C_   256
#define H_   64
#define W_   64
#define BIN_ 16
#define CH_PER_BLK 4

__global__ __launch_bounds__(256, 4)
void roi_feature_kernel(const float* __restrict__ orig,
                        const float* __restrict__ lab,
                        const float* __restrict__ att,
                        float* __restrict__ out)
{
    const int b      = blockIdx.x;           // 0..31
    const int cchunk = blockIdx.y;           // 0..63, 4 channels each
    const int t      = threadIdx.x;          // 0..255
    const int i      = t >> 4;               // bin row  (drives y)
    const int j      = t & 15;               // bin col  (drives x)

    const float* L = lab + b * 5;
    const float l1 = __ldg(L + 1);
    const float l2 = __ldg(L + 2);
    const float l3 = __ldg(L + 3);
    const float l4 = __ldg(L + 4);

    // grid[...,0] -> x pixel (from j); grid[...,1] -> y pixel (from i)
    const float gx = 2.0f * (float)(j - BIN_ / 2) * l3 / (float)BIN_ + (l1 * 2.0f - 1.0f);
    const float gy = 2.0f * (float)(i - BIN_ / 2) * l4 / (float)BIN_ + (l2 * 2.0f - 1.0f);

    const float x = ((gx + 1.0f) * (float)W_ - 1.0f) * 0.5f;
    const float y = ((gy + 1.0f) * (float)H_ - 1.0f) * 0.5f;

    const float x0f = floorf(x);
    const float y0f = floorf(y);
    const int x0 = (int)x0f;
    const int y0 = (int)y0f;
    const int x1 = x0 + 1;
    const int y1 = y0 + 1;

    const float wx1 = x - x0f, wx0 = 1.0f - wx1;
    const float wy1 = y - y0f, wy0 = 1.0f - wy1;

    const float vx0 = (x0 >= 0 && x0 < W_) ? 1.0f : 0.0f;
    const float vx1 = (x1 >= 0 && x1 < W_) ? 1.0f : 0.0f;
    const float vy0 = (y0 >= 0 && y0 < H_) ? 1.0f : 0.0f;
    const float vy1 = (y1 >= 0 && y1 < H_) ? 1.0f : 0.0f;

    const float w00 = wx0 * wy0 * vx0 * vy0;
    const float w01 = wx1 * wy0 * vx1 * vy0;
    const float w10 = wx0 * wy1 * vx0 * vy1;
    const float w11 = wx1 * wy1 * vx1 * vy1;

    const int xc0 = min(max(x0, 0), W_ - 1);
    const int xc1 = min(max(x1, 0), W_ - 1);
    const int yc0 = min(max(y0, 0), H_ - 1);
    const int yc1 = min(max(y1, 0), H_ - 1);

    const int o00 = yc0 * W_ + xc0;
    const int o01 = yc0 * W_ + xc1;
    const int o10 = yc1 * W_ + xc0;
    const int o11 = yc1 * W_ + xc1;

    const size_t plane   = (size_t)H_ * W_;                     // 4096
    const size_t base    = ((size_t)b * C_ + (size_t)cchunk * CH_PER_BLK) * plane;
    const size_t outbase = ((size_t)b * C_ + (size_t)cchunk * CH_PER_BLK) * (BIN_ * BIN_) + t;
    const size_t out2off = (size_t)B_ * C_ * BIN_ * BIN_;       // 2,097,152

    // ---- Phase 1: issue ALL gather loads (32 in flight per thread) ----
    float p[CH_PER_BLK][4];
    float q[CH_PER_BLK][4];

    #pragma unroll
    for (int cc = 0; cc < CH_PER_BLK; ++cc) {
        const float* pp = orig + base + (size_t)cc * plane;
        p[cc][0] = __ldg(pp + o00);
        p[cc][1] = __ldg(pp + o01);
        p[cc][2] = __ldg(pp + o10);
        p[cc][3] = __ldg(pp + o11);
    }
    #pragma unroll
    for (int cc = 0; cc < CH_PER_BLK; ++cc) {
        const float* qq = att + base + (size_t)cc * plane;
        q[cc][0] = __ldg(qq + o00);
        q[cc][1] = __ldg(qq + o01);
        q[cc][2] = __ldg(qq + o10);
        q[cc][3] = __ldg(qq + o11);
    }

    // ---- Phase 2: compute + streaming stores (evict-first in L2) ----
    #pragma unroll
    for (int cc = 0; cc < CH_PER_BLK; ++cc) {
        const float r1 = p[cc][0] * w00 + p[cc][1] * w01 + p[cc][2] * w10 + p[cc][3] * w11;
        const float r2 = q[cc][0] * w00 + q[cc][1] * w01 + q[cc][2] * w10 + q[cc][3] * w11;
        __stcs(out + outbase + (size_t)cc * (BIN_ * BIN_), r1);
        __stcs(out + out2off + outbase + (size_t)cc * (BIN_ * BIN_), r2);
    }
}

extern "C" void kernel_launch(void* const* d_in, const int* in_sizes, int n_in,
                              void* d_out, int out_size)
{
    const float* orig = (const float*)d_in[0];
    const float* lab  = (const float*)d_in[1];
    const float* att  = (const float*)d_in[2];
    float* out        = (float*)d_out;

    dim3 grid(B_, C_ / CH_PER_BLK);   // (32, 64)
    roi_feature_kernel<<<grid, 256>>>(orig, lab, att, out);
}

// round 12
// speedup vs baseline: 1.3409x; 1.0226x over previous
#include <cuda_runtime.h>
#include <cuda_bf16.h>

// roi_feature: dual bilinear grid_sample with a shared 16x16 grid per batch.
// inputs: [0] original_features f32 (32,256,64,64)
//         [1] lab f32 (32,1,5)
//         [2] attack_features f32 (32,256,64,64)
// output: concat(out1, out2), each (32,256,16,16) f32.
//
// R12 strategy: halve L1tex wavefronts per gather LDG via lane remap.
// A full bin-row's x-span is ~124B (1-2 lines), so: warp = ONE bin row
// (j = lane&15) x TWO channels (h = lane>>4). Each corner LDG touches
// 1 y-row x 2 planes ~= 2-4 lines vs 4-8 with the old 2-bin-row warp.
// Warp w covers bin rows w and w+8. The L1tex wavefront queue (~2.07
// cyc/replay-wf, single FIFO per SM) is the hypothesized binding resource.

#define B_   32
#define C_   256
#define H_   64
#define W_   64
#define BIN_ 16
#define CH_PER_BLK 4

__global__ __launch_bounds__(256, 2)
void roi_feature_kernel(const float* __restrict__ orig,
                        const float* __restrict__ lab,
                        const float* __restrict__ att,
                        float* __restrict__ out)
{
    const int b      = blockIdx.x;           // 0..31
    const int cchunk = blockIdx.y;           // 0..63, 4 channels each
    const int t      = threadIdx.x;          // 0..255
    const int w      = t >> 5;               // warp 0..7
    const int lane   = t & 31;
    const int h      = lane >> 4;            // channel half (0/1)
    const int j      = lane & 15;            // bin col (drives x)

    const float* L = lab + b * 5;
    const float l1 = __ldg(L + 1);
    const float l2 = __ldg(L + 2);
    const float l3 = __ldg(L + 3);
    const float l4 = __ldg(L + 4);

    // ---- x side (depends on j only) ----
    const float gx = 2.0f * (float)(j - BIN_ / 2) * l3 / (float)BIN_ + (l1 * 2.0f - 1.0f);
    const float x  = ((gx + 1.0f) * (float)W_ - 1.0f) * 0.5f;
    const float x0f = floorf(x);
    const int x0 = (int)x0f;
    const int x1 = x0 + 1;
    const float wx1 = x - x0f, wx0 = 1.0f - wx1;
    const float vx0 = (x0 >= 0 && x0 < W_) ? 1.0f : 0.0f;
    const float vx1 = (x1 >= 0 && x1 < W_) ? 1.0f : 0.0f;
    const int xc0 = min(max(x0, 0), W_ - 1);
    const int xc1 = min(max(x1, 0), W_ - 1);

    // ---- y side per iter: bin rows w and w+8 ----
    int   o00[2], o01[2], o10[2], o11[2];
    float w00[2], w01[2], w10[2], w11[2];
    #pragma unroll
    for (int it = 0; it < 2; ++it) {
        const int ib = w + 8 * it;
        const float gy = 2.0f * (float)(ib - BIN_ / 2) * l4 / (float)BIN_ + (l2 * 2.0f - 1.0f);
        const float y  = ((gy + 1.0f) * (float)H_ - 1.0f) * 0.5f;
        const float y0f = floorf(y);
        const int y0 = (int)y0f;
        const int y1 = y0 + 1;
        const float wy1 = y - y0f, wy0 = 1.0f - wy1;
        const float vy0 = (y0 >= 0 && y0 < H_) ? 1.0f : 0.0f;
        const float vy1 = (y1 >= 0 && y1 < H_) ? 1.0f : 0.0f;
        const int yc0 = min(max(y0, 0), H_ - 1);
        const int yc1 = min(max(y1, 0), H_ - 1);

        w00[it] = wx0 * wy0 * vx0 * vy0;
        w01[it] = wx1 * wy0 * vx1 * vy0;
        w10[it] = wx0 * wy1 * vx0 * vy1;
        w11[it] = wx1 * wy1 * vx1 * vy1;

        o00[it] = yc0 * W_ + xc0;
        o01[it] = yc0 * W_ + xc1;
        o10[it] = yc1 * W_ + xc0;
        o11[it] = yc1 * W_ + xc1;
    }

    const size_t plane   = (size_t)H_ * W_;                 // 4096
    const size_t out2off = (size_t)B_ * C_ * BIN_ * BIN_;   // 2,097,152

    // channel for this lane in pair ccp: c = cchunk*4 + 2*ccp + h
    const size_t base = ((size_t)b * C_ + (size_t)cchunk * CH_PER_BLK + h) * plane;

    // ---- Phase 1: front-batch all 32 gather loads ----
    float P[2][2][4];   // [iter][ccp][corner]
    float Q[2][2][4];

    #pragma unroll
    for (int it = 0; it < 2; ++it) {
        #pragma unroll
        for (int ccp = 0; ccp < 2; ++ccp) {
            const float* pp = orig + base + (size_t)(2 * ccp) * plane;
            P[it][ccp][0] = __ldg(pp + o00[it]);
            P[it][ccp][1] = __ldg(pp + o01[it]);
            P[it][ccp][2] = __ldg(pp + o10[it]);
            P[it][ccp][3] = __ldg(pp + o11[it]);
        }
    }
    #pragma unroll
    for (int it = 0; it < 2; ++it) {
        #pragma unroll
        for (int ccp = 0; ccp < 2; ++ccp) {
            const float* qq = att + base + (size_t)(2 * ccp) * plane;
            Q[it][ccp][0] = __ldg(qq + o00[it]);
            Q[it][ccp][1] = __ldg(qq + o01[it]);
            Q[it][ccp][2] = __ldg(qq + o10[it]);
            Q[it][ccp][3] = __ldg(qq + o11[it]);
        }
    }

    // ---- Phase 2: compute + store ----
    #pragma unroll
    for (int it = 0; it < 2; ++it) {
        const int ib = w + 8 * it;
        #pragma unroll
        for (int ccp = 0; ccp < 2; ++ccp) {
            const int c = cchunk * CH_PER_BLK + 2 * ccp + h;
            const size_t oidx = ((size_t)b * C_ + c) * (BIN_ * BIN_) + ib * BIN_ + j;
            const float r1 = P[it][ccp][0] * w00[it] + P[it][ccp][1] * w01[it]
                           + P[it][ccp][2] * w10[it] + P[it][ccp][3] * w11[it];
            const float r2 = Q[it][ccp][0] * w00[it] + Q[it][ccp][1] * w01[it]
                           + Q[it][ccp][2] * w10[it] + Q[it][ccp][3] * w11[it];
            out[oidx]           = r1;
            out[out2off + oidx] = r2;
        }
    }
}

extern "C" void kernel_launch(void* const* d_in, const int* in_sizes, int n_in,
                              void* d_out, int out_size)
{
    const float* orig = (const float*)d_in[0];
    const float* lab  = (const float*)d_in[1];
    const float* att  = (const float*)d_in[2];
    float* out        = (float*)d_out;

    dim3 grid(B_, C_ / CH_PER_BLK);   // (32, 64)
    roi_feature_kernel<<<grid, 256>>>(orig, lab, att, out);
}